// round 1
// baseline (speedup 1.0000x reference)
#include <cuda_runtime.h>
#include <math.h>

#define NB    8192
#define DIM   128
#define NTOT  (2*NB)            // 16384
#define INVT  14.2857142857142857f   // 1/0.07

#define BM 128
#define BN 128
#define BK 16
#define NTILES (NTOT/BN)            // 128
#define NCHUNK (NTILES*(DIM/BK))    // 1024

// Scratch (allocation-free contract: __device__ globals)
__device__ float g_reps[(size_t)NTOT * DIM];  // normalized embeddings, 8 MB
__device__ float g_lse[NTOT];
__device__ float g_pos[NB];

// Packed fp32x2 FMA (Blackwell sm_100+/sm_103a)
__device__ __forceinline__ float2 ffma2(float2 a, float2 b, float2 c) {
    union U { float2 f; unsigned long long u; };
    U ua, ub, uc;
    ua.f = a; ub.f = b; uc.f = c;
    asm("fma.rn.f32x2 %0, %1, %2, %0;" : "+l"(uc.u) : "l"(ua.u), "l"(ub.u));
    return uc.f;
}

// ---------------------------------------------------------------------------
// L2-normalize rows of [z_i; z_j] into g_reps. One warp per row.
// ---------------------------------------------------------------------------
__global__ void nt_normalize(const float* __restrict__ zi,
                             const float* __restrict__ zj) {
    int warp = (blockIdx.x * blockDim.x + threadIdx.x) >> 5;
    int lane = threadIdx.x & 31;
    if (warp >= NTOT) return;
    const float* src = (warp < NB) ? (zi + (size_t)warp * DIM)
                                   : (zj + (size_t)(warp - NB) * DIM);
    float4 v = ((const float4*)src)[lane];
    float ss = v.x*v.x + v.y*v.y + v.z*v.z + v.w*v.w;
#pragma unroll
    for (int o = 16; o; o >>= 1) ss += __shfl_xor_sync(0xffffffffu, ss, o);
    float inv = 1.0f / fmaxf(sqrtf(ss), 1e-12f);
    float4 ov = make_float4(v.x*inv, v.y*inv, v.z*inv, v.w*inv);
    ((float4*)(g_reps + (size_t)warp * DIM))[lane] = ov;
}

// ---------------------------------------------------------------------------
// Positive-pair logits: pos[i] = exp(dot(reps[i], reps[i+NB]) / T)
// ---------------------------------------------------------------------------
__global__ void nt_pos() {
    int warp = (blockIdx.x * blockDim.x + threadIdx.x) >> 5;
    int lane = threadIdx.x & 31;
    if (warp >= NB) return;
    float4 a = ((const float4*)(g_reps + (size_t)warp * DIM))[lane];
    float4 b = ((const float4*)(g_reps + (size_t)(warp + NB) * DIM))[lane];
    float d = a.x*b.x + a.y*b.y + a.z*b.z + a.w*b.w;
#pragma unroll
    for (int o = 16; o; o >>= 1) d += __shfl_xor_sync(0xffffffffu, d, o);
    if (lane == 0) g_pos[warp] = expf(d * INVT);
}

// ---------------------------------------------------------------------------
// Fused GEMM + double-logsumexp row reduction.
// Per CTA: 128 rows. A block persistent in smem; B tiles double-buffered.
// Online state per row (sim-domain): M = max sim (diag masked),
// S = sum_j exp(exp(sim_j) - exp(M)), thr = log(exp(M)-25) skip threshold.
// ---------------------------------------------------------------------------
__global__ void __launch_bounds__(256, 1) nt_main() {
    extern __shared__ char smem_raw[];
    float  (*As)[BM]      = (float (*)[BM])smem_raw;                   // 64 KB
    float2 (*Bs)[BK][BN]  = (float2 (*)[BK][BN])(smem_raw + 65536);    // 32 KB (2 bufs)
    float*  shRed         = (float*)(smem_raw + 65536);                // reuse after loop

    const int tid = threadIdx.x;
    const int tx  = tid & 15;
    const int ty  = tid >> 4;
    const int ty8 = ty * 8;
    const int r0  = blockIdx.x * BM;

    // ---- persistent A block: As[k][m] = reps[r0+m][k] (fill conflicts: one-time)
#pragma unroll
    for (int it = 0; it < 16; ++it) {
        int f4 = tid + it * 256;      // 0..4095
        int m  = f4 >> 5;             // 0..127
        int kq = f4 & 31;             // 0..31
        float4 v = *(const float4*)(g_reps + (size_t)(r0 + m) * DIM + kq * 4);
        As[kq*4+0][m] = v.x; As[kq*4+1][m] = v.y;
        As[kq*4+2][m] = v.z; As[kq*4+3][m] = v.w;
    }

    // fixed per-thread B-load coordinates
    const int f4a = tid * 2, f4b = tid * 2 + 1;
    const int na = f4a >> 2, ka = (f4a & 3) * 4;
    const int nb = f4b >> 2, kb = (f4b & 3) * 4;

    float2 acc[4][8];
#pragma unroll
    for (int p = 0; p < 4; ++p)
#pragma unroll
        for (int j = 0; j < 8; ++j) acc[p][j] = make_float2(0.f, 0.f);

    float Mx[8], Sx[8], thr[8];
#pragma unroll
    for (int i = 0; i < 8; ++i) { Mx[i] = -1e30f; Sx[i] = 0.f; thr[i] = -1e30f; }

    // prolog: chunk 0 into buffer 0
    {
        float4 va = *(const float4*)(g_reps + (size_t)na * DIM + ka);
        float4 vb = *(const float4*)(g_reps + (size_t)nb * DIM + kb);
        Bs[0][ka+0][na] = make_float2(va.x, va.x); Bs[0][ka+1][na] = make_float2(va.y, va.y);
        Bs[0][ka+2][na] = make_float2(va.z, va.z); Bs[0][ka+3][na] = make_float2(va.w, va.w);
        Bs[0][kb+0][nb] = make_float2(vb.x, vb.x); Bs[0][kb+1][nb] = make_float2(vb.y, vb.y);
        Bs[0][kb+2][nb] = make_float2(vb.z, vb.z); Bs[0][kb+3][nb] = make_float2(vb.w, vb.w);
    }
    __syncthreads();

    for (int c = 0; c < NCHUNK; ++c) {
        const int buf = c & 1;

        // prefetch next chunk into registers (latency hidden by compute)
        float4 nva, nvb;
        if (c + 1 < NCHUNK) {
            int t1 = (c + 1) >> 3;
            int cc0 = t1 * BN;
            int kk0 = ((c + 1) & 7) * BK;
            nva = *(const float4*)(g_reps + (size_t)(cc0 + na) * DIM + kk0 + ka);
            nvb = *(const float4*)(g_reps + (size_t)(cc0 + nb) * DIM + kk0 + kb);
        }

        // ---- compute: 16 k-steps, 32 FFMA2 each
        const int k0 = (c & 7) * BK;
#pragma unroll
        for (int kk = 0; kk < BK; ++kk) {
            const int k = k0 + kk;
            float4 a0 = *(const float4*)&As[k][ty8];
            float4 a1 = *(const float4*)&As[k][ty8 + 4];
            float2 pa[4];
            pa[0] = make_float2(a0.x, a0.y); pa[1] = make_float2(a0.z, a0.w);
            pa[2] = make_float2(a1.x, a1.y); pa[3] = make_float2(a1.z, a1.w);
            float2 bj[8];
#pragma unroll
            for (int j = 0; j < 8; ++j) bj[j] = Bs[buf][kk][j * 16 + tx];
#pragma unroll
            for (int p = 0; p < 4; ++p)
#pragma unroll
                for (int j = 0; j < 8; ++j)
                    acc[p][j] = ffma2(pa[p], bj[j], acc[p][j]);
        }

        // ---- epilogue at each N-tile boundary
        if ((c & 7) == 7) {
            const int c0 = (c >> 3) * BN;
#pragma unroll
            for (int li = 0; li < 8; ++li) {
                const int p = li >> 1;
                const int grow = r0 + ty8 + li;
                float v[8];
                float tmax = -1e30f;
#pragma unroll
                for (int j = 0; j < 8; ++j) {
                    float s = ((li & 1) ? acc[p][j].y : acc[p][j].x) * INVT;
                    if (c0 + j * 16 + tx == grow) s = -1e30f;   // mask diagonal
                    v[j] = s;
                    tmax = fmaxf(tmax, s);
                }
                if (tmax > Mx[li]) {
                    float mo = __expf(Mx[li]);
                    float mn = __expf(tmax);
                    Sx[li] *= __expf(mo - mn);    // rescale old sum; underflows to 0 safely
                    Mx[li] = tmax;
                    thr[li] = (mn > 26.f) ? __logf(mn - 25.f) : -1e30f;
                }
#pragma unroll
                for (int j = 0; j < 8; ++j) {
                    if (v[j] > thr[li]) {         // rare: only near-max sims pass
                        Sx[li] += __expf(__expf(v[j]) - __expf(Mx[li]));
                    }
                }
            }
#pragma unroll
            for (int p = 0; p < 4; ++p)
#pragma unroll
                for (int j = 0; j < 8; ++j) acc[p][j] = make_float2(0.f, 0.f);
        }

        __syncthreads();                          // everyone done reading buf
        if (c + 1 < NCHUNK) {
            const int nbuf = buf ^ 1;
            Bs[nbuf][ka+0][na] = make_float2(nva.x, nva.x); Bs[nbuf][ka+1][na] = make_float2(nva.y, nva.y);
            Bs[nbuf][ka+2][na] = make_float2(nva.z, nva.z); Bs[nbuf][ka+3][na] = make_float2(nva.w, nva.w);
            Bs[nbuf][kb+0][nb] = make_float2(nvb.x, nvb.x); Bs[nbuf][kb+1][nb] = make_float2(nvb.y, nvb.y);
            Bs[nbuf][kb+2][nb] = make_float2(nvb.z, nvb.z); Bs[nbuf][kb+3][nb] = make_float2(nvb.w, nvb.w);
            __syncthreads();
        }
    }

    // ---- combine (M,S) across the 16 threads sharing each row
    __syncthreads();
#pragma unroll
    for (int li = 0; li < 8; ++li) {
        shRed[(ty8 + li) * 16 + tx]        = Mx[li];
        shRed[2048 + (ty8 + li) * 16 + tx] = Sx[li];
    }
    __syncthreads();
    if (tid < 128) {
        float bm = -1e30f, bs = 0.f;
        for (int t = 0; t < 16; ++t) {
            float Mi = shRed[tid * 16 + t];
            float Si = shRed[2048 + tid * 16 + t];
            if (Mi > bm) {
                bs = bs * __expf(__expf(bm) - __expf(Mi)) + Si;
                bm = Mi;
            } else {
                bs += Si * __expf(__expf(Mi) - __expf(bm));
            }
        }
        // lse = exp(M_sim) + log(S)
        g_lse[r0 + tid] = __expf(bm) + logf(bs);
    }
}

// ---------------------------------------------------------------------------
// Final scalar: mean(lse - pos). fp64 accumulation (only 16384 terms).
// ---------------------------------------------------------------------------
__global__ void nt_finalize(float* __restrict__ out) {
    __shared__ double red[256];
    double acc = 0.0;
    for (int i = threadIdx.x; i < NTOT; i += 256) {
        float pos = g_pos[(i < NB) ? i : (i - NB)];
        acc += (double)g_lse[i] - (double)pos;
    }
    red[threadIdx.x] = acc;
    __syncthreads();
    for (int s = 128; s; s >>= 1) {
        if (threadIdx.x < s) red[threadIdx.x] += red[threadIdx.x + s];
        __syncthreads();
    }
    if (threadIdx.x == 0) out[0] = (float)(red[0] / (double)NTOT);
}

// ---------------------------------------------------------------------------
extern "C" void kernel_launch(void* const* d_in, const int* in_sizes, int n_in,
                              void* d_out, int out_size) {
    const float* zi = (const float*)d_in[0];
    const float* zj = (const float*)d_in[1];
    float* out = (float*)d_out;

    cudaFuncSetAttribute(nt_main, cudaFuncAttributeMaxDynamicSharedMemorySize, 98304);

    nt_normalize<<<NTOT / 8, 256>>>(zi, zj);
    nt_pos<<<NB / 8, 256>>>();
    nt_main<<<NTILES, 256, 98304>>>();
    nt_finalize<<<1, 256>>>(out);
}

// round 2
// speedup vs baseline: 2.2894x; 2.2894x over previous
#include <cuda_runtime.h>
#include <math.h>
#include <stdint.h>

#define NB    8192
#define DIM   128
#define NTOT  (2*NB)                 // 16384
#define INVT  14.285714285714286f    // 1/0.07

#define BM 128
#define BN 256
#define NTILE  (NTOT/BN)             // 64 N-tiles per CTA
#define NCHUNK (NTILE*4)             // 256 K-chunks (K=128 in 4 chunks of 32)

#define SA 132                        // A smem row stride (floats): 132 mod 32 = 4 -> conflict-free frags
#define SB 36                         // B smem row stride (floats): 36 mod 32 = 4
#define A_FLOATS (BM*SA)              // 16896
#define B_FLOATS (BN*SB)              // 9216 per buffer

// Scratch (__device__ globals: allocation-free contract)
__device__ float g_reps[(size_t)NTOT * DIM];   // tf32-rounded normalized embeddings (8 MB, L2-resident)
__device__ float g_lse[NTOT];
__device__ float g_pos[NB];

// ---------------------------------------------------------------------------
__device__ __forceinline__ uint32_t cvta_smem(const void* p) {
    uint32_t r;
    asm("{ .reg .u64 t; cvta.to.shared.u64 t, %1; cvt.u32.u64 %0, t; }" : "=r"(r) : "l"(p));
    return r;
}
__device__ __forceinline__ void cp16(uint32_t dst, const void* src) {
    asm volatile("cp.async.cg.shared.global [%0], [%1], 16;" :: "r"(dst), "l"(src));
}
__device__ __forceinline__ void cp_commit() { asm volatile("cp.async.commit_group;"); }
__device__ __forceinline__ void cp_wait0()  { asm volatile("cp.async.wait_group 0;"); }

__device__ __forceinline__ float tf32_rna(float x) {
    uint32_t t;
    asm("cvt.rna.tf32.f32 %0, %1;" : "=r"(t) : "f"(x));
    return __uint_as_float(t);
}

__device__ __forceinline__ void mma_tf32(float c[4],
                                         uint32_t a0, uint32_t a1, uint32_t a2, uint32_t a3,
                                         uint32_t b0, uint32_t b1) {
    asm volatile(
        "mma.sync.aligned.m16n8k8.row.col.f32.tf32.tf32.f32 "
        "{%0,%1,%2,%3}, {%4,%5,%6,%7}, {%8,%9}, {%0,%1,%2,%3};"
        : "+f"(c[0]), "+f"(c[1]), "+f"(c[2]), "+f"(c[3])
        : "r"(a0), "r"(a1), "r"(a2), "r"(a3), "r"(b0), "r"(b1));
}

// ---------------------------------------------------------------------------
// L2-normalize rows of [z_i; z_j] into g_reps, rounding to tf32 (rna) so the
// HMMA sees round-to-nearest inputs (no truncation bias). One warp per row.
// ---------------------------------------------------------------------------
__global__ void nt_normalize(const float* __restrict__ zi,
                             const float* __restrict__ zj) {
    int warp = (blockIdx.x * blockDim.x + threadIdx.x) >> 5;
    int lane = threadIdx.x & 31;
    if (warp >= NTOT) return;
    const float* src = (warp < NB) ? (zi + (size_t)warp * DIM)
                                   : (zj + (size_t)(warp - NB) * DIM);
    float4 v = ((const float4*)src)[lane];
    float ss = v.x*v.x + v.y*v.y + v.z*v.z + v.w*v.w;
#pragma unroll
    for (int o = 16; o; o >>= 1) ss += __shfl_xor_sync(0xffffffffu, ss, o);
    float inv = 1.0f / fmaxf(sqrtf(ss), 1e-12f);
    float4 ov = make_float4(tf32_rna(v.x*inv), tf32_rna(v.y*inv),
                            tf32_rna(v.z*inv), tf32_rna(v.w*inv));
    ((float4*)(g_reps + (size_t)warp * DIM))[lane] = ov;
}

// ---------------------------------------------------------------------------
// Positive-pair logits: pos[i] = exp(dot(reps[i], reps[i+NB]) / T)  (fp32 dot)
// ---------------------------------------------------------------------------
__global__ void nt_pos() {
    int warp = (blockIdx.x * blockDim.x + threadIdx.x) >> 5;
    int lane = threadIdx.x & 31;
    if (warp >= NB) return;
    float4 a = ((const float4*)(g_reps + (size_t)warp * DIM))[lane];
    float4 b = ((const float4*)(g_reps + (size_t)(warp + NB) * DIM))[lane];
    float d = a.x*b.x + a.y*b.y + a.z*b.z + a.w*b.w;
#pragma unroll
    for (int o = 16; o; o >>= 1) d += __shfl_xor_sync(0xffffffffu, d, o);
    if (lane == 0) g_pos[warp] = expf(d * INVT);
}

// ---------------------------------------------------------------------------
// Fused TF32-HMMA GEMM + online double-logsumexp.
// CTA: 128 rows x (sweep of 256-col tiles). 8 warps = 2(M) x 4(N),
// warp tile 64x64, mma m16n8k8, K=128 via 4 cp.async-double-buffered chunks.
// ---------------------------------------------------------------------------
__global__ void __launch_bounds__(256, 1) nt_main() {
    extern __shared__ float sm[];
    float* As = sm;                    // [128][SA]
    float* Bs = sm + A_FLOATS;         // 2 x [256][SB]

    const int tid   = threadIdx.x;
    const int lane  = tid & 31;
    const int wid   = tid >> 5;
    const int warpM = wid >> 2;        // 0..1
    const int warpN = wid & 3;         // 0..3
    const int qt    = lane & 3;        // k-quad / col-pair index
    const int rt    = lane >> 2;       // row-in-frag / n-in-frag
    const int r0    = blockIdx.x * BM;

    const uint32_t sA = cvta_smem(As);
    const uint32_t sB = cvta_smem(Bs);

    // ---- A block (128x128) -> smem via cp.async (16 x 16B per thread)
#pragma unroll
    for (int i = 0; i < 16; ++i) {
        int u = tid + i * 256;          // 0..4095
        int r = u >> 5, kq = u & 31;
        cp16(sA + (uint32_t)(r * SA + kq * 4) * 4,
             g_reps + (size_t)(r0 + r) * DIM + kq * 4);
    }
    // ---- B chunk 0 (ntile 0, kc 0) -> buffer 0
#pragma unroll
    for (int i = 0; i < 8; ++i) {
        int u = tid + i * 256;          // 0..2047
        int n = u >> 3, kq = u & 7;
        cp16(sB + (uint32_t)(n * SB + kq * 4) * 4,
             g_reps + (size_t)n * DIM + kq * 4);
    }
    cp_commit();

    float C[4][8][4];
#pragma unroll
    for (int mt = 0; mt < 4; ++mt)
#pragma unroll
        for (int nt = 0; nt < 8; ++nt)
#pragma unroll
            for (int e = 0; e < 4; ++e) C[mt][nt][e] = 0.f;

    float Mx[8], Sx[8], thr[8];
#pragma unroll
    for (int s = 0; s < 8; ++s) { Mx[s] = -1e30f; Sx[s] = 0.f; thr[s] = -1e30f; }

    for (int c = 0; c < NCHUNK; ++c) {
        const int buf = c & 1;
        cp_wait0();
        __syncthreads();                 // chunk c ready; everyone done with buf^1

        // prefetch chunk c+1 into buf^1
        if (c + 1 < NCHUNK) {
            const int cn = c + 1;
            const int pc0 = (cn >> 2) * BN;
            const int pkc = cn & 3;
            const uint32_t dB = sB + (uint32_t)((buf ^ 1) * B_FLOATS) * 4;
#pragma unroll
            for (int i = 0; i < 8; ++i) {
                int u = tid + i * 256;
                int n = u >> 3, kq = u & 7;
                cp16(dB + (uint32_t)(n * SB + kq * 4) * 4,
                     g_reps + (size_t)(pc0 + n) * DIM + pkc * 32 + kq * 4);
            }
        }
        cp_commit();

        // ---- compute chunk c: 4 k8-steps
        const int kc = c & 3;
        const float* Bb = Bs + buf * B_FLOATS;
#pragma unroll
        for (int kk = 0; kk < 4; ++kk) {
            const int kA = kc * 32 + kk * 8;
            const int kB = kk * 8;
            uint32_t a[4][4];
#pragma unroll
            for (int mt = 0; mt < 4; ++mt) {
                const float* ap = As + (warpM * 64 + mt * 16 + rt) * SA + kA + qt;
                a[mt][0] = __float_as_uint(ap[0]);
                a[mt][2] = __float_as_uint(ap[4]);
                a[mt][1] = __float_as_uint(ap[8 * SA]);
                a[mt][3] = __float_as_uint(ap[8 * SA + 4]);
            }
            uint32_t b[8][2];
#pragma unroll
            for (int nt = 0; nt < 8; ++nt) {
                const float* bp = Bb + (warpN * 64 + nt * 8 + rt) * SB + kB + qt;
                b[nt][0] = __float_as_uint(bp[0]);
                b[nt][1] = __float_as_uint(bp[4]);
            }
#pragma unroll
            for (int mt = 0; mt < 4; ++mt)
#pragma unroll
                for (int nt = 0; nt < 8; ++nt)
                    mma_tf32(C[mt][nt], a[mt][0], a[mt][1], a[mt][2], a[mt][3],
                             b[nt][0], b[nt][1]);
        }

        // ---- epilogue: full K=128 accumulated for this 256-col tile
        if (kc == 3) {
            const int c0 = (c >> 2) * BN;
#pragma unroll
            for (int s = 0; s < 8; ++s) {
                const int mt = s >> 1, h = s & 1;
                const int grow = r0 + warpM * 64 + mt * 16 + rt + 8 * h;
                float v[16];
                float tmax = -1e30f;
#pragma unroll
                for (int nt = 0; nt < 8; ++nt) {
#pragma unroll
                    for (int e = 0; e < 2; ++e) {
                        float sv = C[mt][nt][h * 2 + e] * INVT;
                        int col = c0 + warpN * 64 + nt * 8 + 2 * qt + e;
                        if (col == grow) sv = -1e30f;      // mask diagonal
                        v[nt * 2 + e] = sv;
                        tmax = fmaxf(tmax, sv);
                    }
                }
                if (tmax > Mx[s]) {
                    float mo = __expf(Mx[s]);
                    float mn = __expf(tmax);
                    Sx[s] *= __expf(mo - mn);              // underflows safely
                    Mx[s] = tmax;
                    thr[s] = (mn > 26.f) ? __logf(mn - 25.f) : -1e30f;
                }
                const float eM = __expf(Mx[s]);
#pragma unroll
                for (int j = 0; j < 16; ++j) {
                    if (v[j] > thr[s]) {                   // rare: only near-max sims
                        Sx[s] += __expf(__expf(v[j]) - eM);
                    }
                }
            }
#pragma unroll
            for (int mt = 0; mt < 4; ++mt)
#pragma unroll
                for (int nt = 0; nt < 8; ++nt)
#pragma unroll
                    for (int e = 0; e < 4; ++e) C[mt][nt][e] = 0.f;
        }
    }

    // ---- combine (M,S): 16 partials per row (4 N-warps x 4 lane-cols)
    __syncthreads();
    float* shM = sm;
    float* shS = sm + 2048;
#pragma unroll
    for (int s = 0; s < 8; ++s) {
        const int mt = s >> 1, h = s & 1;
        const int lrow = warpM * 64 + mt * 16 + rt + 8 * h;
        shM[lrow * 16 + warpN * 4 + qt] = Mx[s];
        shS[lrow * 16 + warpN * 4 + qt] = Sx[s];
    }
    __syncthreads();
    if (tid < 128) {
        float bm = -1e30f, bs = 0.f;
#pragma unroll
        for (int t = 0; t < 16; ++t) {
            float Mi = shM[tid * 16 + t];
            float Si = shS[tid * 16 + t];
            if (Mi > bm) {
                bs = bs * __expf(__expf(bm) - __expf(Mi)) + Si;
                bm = Mi;
            } else {
                bs += Si * __expf(__expf(Mi) - __expf(bm));
            }
        }
        g_lse[r0 + tid] = __expf(bm) + logf(bs);   // lse = e_max + log(S)
    }
}

// ---------------------------------------------------------------------------
// Final scalar: mean(lse - pos), fp64 accumulation.
// ---------------------------------------------------------------------------
__global__ void nt_finalize(float* __restrict__ out) {
    __shared__ double red[256];
    double acc = 0.0;
    for (int i = threadIdx.x; i < NTOT; i += 256) {
        float pos = g_pos[(i < NB) ? i : (i - NB)];
        acc += (double)g_lse[i] - (double)pos;
    }
    red[threadIdx.x] = acc;
    __syncthreads();
    for (int s = 128; s; s >>= 1) {
        if (threadIdx.x < s) red[threadIdx.x] += red[threadIdx.x + s];
        __syncthreads();
    }
    if (threadIdx.x == 0) out[0] = (float)(red[0] / (double)NTOT);
}

// ---------------------------------------------------------------------------
extern "C" void kernel_launch(void* const* d_in, const int* in_sizes, int n_in,
                              void* d_out, int out_size) {
    const float* zi = (const float*)d_in[0];
    const float* zj = (const float*)d_in[1];
    float* out = (float*)d_out;

    const int smem_bytes = (A_FLOATS + 2 * B_FLOATS) * 4;   // 141312
    cudaFuncSetAttribute(nt_main, cudaFuncAttributeMaxDynamicSharedMemorySize, smem_bytes);

    nt_normalize<<<NTOT / 8, 256>>>(zi, zj);
    nt_pos<<<NB / 8, 256>>>();
    nt_main<<<NTOT / BM, 256, smem_bytes>>>();
    nt_finalize<<<1, 256>>>(out);
}

// round 3
// speedup vs baseline: 2.2945x; 1.0022x over previous
#include <cuda_runtime.h>
#include <math.h>
#include <stdint.h>

#define NB    8192
#define DIM   128
#define NTOT  (2*NB)                 // 16384
#define INVT  14.285714285714286f    // 1/0.07

#define BM 128
#define BN 256
#define NTILE  (NTOT/BN)             // 64 N-tiles per CTA
#define NCHUNK (NTILE*4)             // 256 K-chunks (K=128 in 4 chunks of 32)

#define SA 132                        // A smem row stride (floats): 132 mod 32 = 4 -> conflict-free frags
#define SB 36                         // B smem row stride (floats): 36 mod 32 = 4
#define A_FLOATS (BM*SA)              // 16896
#define B_FLOATS (BN*SB)              // 9216 per buffer

// Scratch (__device__ globals: allocation-free contract)
__device__ float g_reps[(size_t)NTOT * DIM];   // tf32-rounded normalized embeddings (8 MB, L2-resident)
__device__ float g_lse[NTOT];
__device__ float g_pos[NB];

// ---------------------------------------------------------------------------
__device__ __forceinline__ uint32_t cvta_smem(const void* p) {
    uint32_t r;
    asm("{ .reg .u64 t; cvta.to.shared.u64 t, %1; cvt.u32.u64 %0, t; }" : "=r"(r) : "l"(p));
    return r;
}
__device__ __forceinline__ void cp16(uint32_t dst, const void* src) {
    asm volatile("cp.async.cg.shared.global [%0], [%1], 16;" :: "r"(dst), "l"(src));
}
__device__ __forceinline__ void cp_commit() { asm volatile("cp.async.commit_group;"); }
__device__ __forceinline__ void cp_wait0()  { asm volatile("cp.async.wait_group 0;"); }

__device__ __forceinline__ float tf32_rna(float x) {
    uint32_t t;
    asm("cvt.rna.tf32.f32 %0, %1;" : "=r"(t) : "f"(x));
    return __uint_as_float(t);
}

__device__ __forceinline__ void mma_tf32(float c[4],
                                         uint32_t a0, uint32_t a1, uint32_t a2, uint32_t a3,
                                         uint32_t b0, uint32_t b1) {
    asm volatile(
        "mma.sync.aligned.m16n8k8.row.col.f32.tf32.tf32.f32 "
        "{%0,%1,%2,%3}, {%4,%5,%6,%7}, {%8,%9}, {%0,%1,%2,%3};"
        : "+f"(c[0]), "+f"(c[1]), "+f"(c[2]), "+f"(c[3])
        : "r"(a0), "r"(a1), "r"(a2), "r"(a3), "r"(b0), "r"(b1));
}

// ---------------------------------------------------------------------------
// L2-normalize rows of [z_i; z_j] into g_reps, rounding to tf32 (rna) so the
// HMMA sees round-to-nearest inputs (no truncation bias). One warp per row.
// ---------------------------------------------------------------------------
__global__ void nt_normalize(const float* __restrict__ zi,
                             const float* __restrict__ zj) {
    int warp = (blockIdx.x * blockDim.x + threadIdx.x) >> 5;
    int lane = threadIdx.x & 31;
    if (warp >= NTOT) return;
    const float* src = (warp < NB) ? (zi + (size_t)warp * DIM)
                                   : (zj + (size_t)(warp - NB) * DIM);
    float4 v = ((const float4*)src)[lane];
    float ss = v.x*v.x + v.y*v.y + v.z*v.z + v.w*v.w;
#pragma unroll
    for (int o = 16; o; o >>= 1) ss += __shfl_xor_sync(0xffffffffu, ss, o);
    float inv = 1.0f / fmaxf(sqrtf(ss), 1e-12f);
    float4 ov = make_float4(tf32_rna(v.x*inv), tf32_rna(v.y*inv),
                            tf32_rna(v.z*inv), tf32_rna(v.w*inv));
    ((float4*)(g_reps + (size_t)warp * DIM))[lane] = ov;
}

// ---------------------------------------------------------------------------
// Positive-pair logits: pos[i] = exp(dot(reps[i], reps[i+NB]) / T)  (fp32 dot)
// ---------------------------------------------------------------------------
__global__ void nt_pos() {
    int warp = (blockIdx.x * blockDim.x + threadIdx.x) >> 5;
    int lane = threadIdx.x & 31;
    if (warp >= NB) return;
    float4 a = ((const float4*)(g_reps + (size_t)warp * DIM))[lane];
    float4 b = ((const float4*)(g_reps + (size_t)(warp + NB) * DIM))[lane];
    float d = a.x*b.x + a.y*b.y + a.z*b.z + a.w*b.w;
#pragma unroll
    for (int o = 16; o; o >>= 1) d += __shfl_xor_sync(0xffffffffu, d, o);
    if (lane == 0) g_pos[warp] = expf(d * INVT);
}

// ---------------------------------------------------------------------------
// Fused TF32-HMMA GEMM + online double-logsumexp.
// CTA: 128 rows x (sweep of 256-col tiles). 8 warps = 2(M) x 4(N),
// warp tile 64x64, mma m16n8k8, K=128 via 4 cp.async-double-buffered chunks.
// ---------------------------------------------------------------------------
__global__ void __launch_bounds__(256, 1) nt_main() {
    extern __shared__ float sm[];
    float* As = sm;                    // [128][SA]
    float* Bs = sm + A_FLOATS;         // 2 x [256][SB]

    const int tid   = threadIdx.x;
    const int lane  = tid & 31;
    const int wid   = tid >> 5;
    const int warpM = wid >> 2;        // 0..1
    const int warpN = wid & 3;         // 0..3
    const int qt    = lane & 3;        // k-quad / col-pair index
    const int rt    = lane >> 2;       // row-in-frag / n-in-frag
    const int r0    = blockIdx.x * BM;

    const uint32_t sA = cvta_smem(As);
    const uint32_t sB = cvta_smem(Bs);

    // ---- A block (128x128) -> smem via cp.async (16 x 16B per thread)
#pragma unroll
    for (int i = 0; i < 16; ++i) {
        int u = tid + i * 256;          // 0..4095
        int r = u >> 5, kq = u & 31;
        cp16(sA + (uint32_t)(r * SA + kq * 4) * 4,
             g_reps + (size_t)(r0 + r) * DIM + kq * 4);
    }
    // ---- B chunk 0 (ntile 0, kc 0) -> buffer 0
#pragma unroll
    for (int i = 0; i < 8; ++i) {
        int u = tid + i * 256;          // 0..2047
        int n = u >> 3, kq = u & 7;
        cp16(sB + (uint32_t)(n * SB + kq * 4) * 4,
             g_reps + (size_t)n * DIM + kq * 4);
    }
    cp_commit();

    float C[4][8][4];
#pragma unroll
    for (int mt = 0; mt < 4; ++mt)
#pragma unroll
        for (int nt = 0; nt < 8; ++nt)
#pragma unroll
            for (int e = 0; e < 4; ++e) C[mt][nt][e] = 0.f;

    float Mx[8], Sx[8], thr[8];
#pragma unroll
    for (int s = 0; s < 8; ++s) { Mx[s] = -1e30f; Sx[s] = 0.f; thr[s] = -1e30f; }

    for (int c = 0; c < NCHUNK; ++c) {
        const int buf = c & 1;
        cp_wait0();
        __syncthreads();                 // chunk c ready; everyone done with buf^1

        // prefetch chunk c+1 into buf^1
        if (c + 1 < NCHUNK) {
            const int cn = c + 1;
            const int pc0 = (cn >> 2) * BN;
            const int pkc = cn & 3;
            const uint32_t dB = sB + (uint32_t)((buf ^ 1) * B_FLOATS) * 4;
#pragma unroll
            for (int i = 0; i < 8; ++i) {
                int u = tid + i * 256;
                int n = u >> 3, kq = u & 7;
                cp16(dB + (uint32_t)(n * SB + kq * 4) * 4,
                     g_reps + (size_t)(pc0 + n) * DIM + pkc * 32 + kq * 4);
            }
        }
        cp_commit();

        // ---- compute chunk c: 4 k8-steps
        const int kc = c & 3;
        const float* Bb = Bs + buf * B_FLOATS;
#pragma unroll
        for (int kk = 0; kk < 4; ++kk) {
            const int kA = kc * 32 + kk * 8;
            const int kB = kk * 8;
            uint32_t a[4][4];
#pragma unroll
            for (int mt = 0; mt < 4; ++mt) {
                const float* ap = As + (warpM * 64 + mt * 16 + rt) * SA + kA + qt;
                a[mt][0] = __float_as_uint(ap[0]);
                a[mt][2] = __float_as_uint(ap[4]);
                a[mt][1] = __float_as_uint(ap[8 * SA]);
                a[mt][3] = __float_as_uint(ap[8 * SA + 4]);
            }
            uint32_t b[8][2];
#pragma unroll
            for (int nt = 0; nt < 8; ++nt) {
                const float* bp = Bb + (warpN * 64 + nt * 8 + rt) * SB + kB + qt;
                b[nt][0] = __float_as_uint(bp[0]);
                b[nt][1] = __float_as_uint(bp[4]);
            }
#pragma unroll
            for (int mt = 0; mt < 4; ++mt)
#pragma unroll
                for (int nt = 0; nt < 8; ++nt)
                    mma_tf32(C[mt][nt], a[mt][0], a[mt][1], a[mt][2], a[mt][3],
                             b[nt][0], b[nt][1]);
        }

        // ---- epilogue: full K=128 accumulated for this 256-col tile
        if (kc == 3) {
            const int c0 = (c >> 2) * BN;
#pragma unroll
            for (int s = 0; s < 8; ++s) {
                const int mt = s >> 1, h = s & 1;
                const int grow = r0 + warpM * 64 + mt * 16 + rt + 8 * h;
                float v[16];
                float tmax = -1e30f;
#pragma unroll
                for (int nt = 0; nt < 8; ++nt) {
#pragma unroll
                    for (int e = 0; e < 2; ++e) {
                        float sv = C[mt][nt][h * 2 + e] * INVT;
                        int col = c0 + warpN * 64 + nt * 8 + 2 * qt + e;
                        if (col == grow) sv = -1e30f;      // mask diagonal
                        v[nt * 2 + e] = sv;
                        tmax = fmaxf(tmax, sv);
                    }
                }
                if (tmax > Mx[s]) {
                    float mo = __expf(Mx[s]);
                    float mn = __expf(tmax);
                    Sx[s] *= __expf(mo - mn);              // underflows safely
                    Mx[s] = tmax;
                    thr[s] = (mn > 26.f) ? __logf(mn - 25.f) : -1e30f;
                }
                const float eM = __expf(Mx[s]);
#pragma unroll
                for (int j = 0; j < 16; ++j) {
                    if (v[j] > thr[s]) {                   // rare: only near-max sims
                        Sx[s] += __expf(__expf(v[j]) - eM);
                    }
                }
            }
#pragma unroll
            for (int mt = 0; mt < 4; ++mt)
#pragma unroll
                for (int nt = 0; nt < 8; ++nt)
#pragma unroll
                    for (int e = 0; e < 4; ++e) C[mt][nt][e] = 0.f;
        }
    }

    // ---- combine (M,S): 16 partials per row (4 N-warps x 4 lane-cols)
    __syncthreads();
    float* shM = sm;
    float* shS = sm + 2048;
#pragma unroll
    for (int s = 0; s < 8; ++s) {
        const int mt = s >> 1, h = s & 1;
        const int lrow = warpM * 64 + mt * 16 + rt + 8 * h;
        shM[lrow * 16 + warpN * 4 + qt] = Mx[s];
        shS[lrow * 16 + warpN * 4 + qt] = Sx[s];
    }
    __syncthreads();
    if (tid < 128) {
        float bm = -1e30f, bs = 0.f;
#pragma unroll
        for (int t = 0; t < 16; ++t) {
            float Mi = shM[tid * 16 + t];
            float Si = shS[tid * 16 + t];
            if (Mi > bm) {
                bs = bs * __expf(__expf(bm) - __expf(Mi)) + Si;
                bm = Mi;
            } else {
                bs += Si * __expf(__expf(Mi) - __expf(bm));
            }
        }
        g_lse[r0 + tid] = __expf(bm) + logf(bs);   // lse = e_max + log(S)
    }
}

// ---------------------------------------------------------------------------
// Final scalar: mean(lse - pos), fp64 accumulation.
// ---------------------------------------------------------------------------
__global__ void nt_finalize(float* __restrict__ out) {
    __shared__ double red[256];
    double acc = 0.0;
    for (int i = threadIdx.x; i < NTOT; i += 256) {
        float pos = g_pos[(i < NB) ? i : (i - NB)];
        acc += (double)g_lse[i] - (double)pos;
    }
    red[threadIdx.x] = acc;
    __syncthreads();
    for (int s = 128; s; s >>= 1) {
        if (threadIdx.x < s) red[threadIdx.x] += red[threadIdx.x + s];
        __syncthreads();
    }
    if (threadIdx.x == 0) out[0] = (float)(red[0] / (double)NTOT);
}

// ---------------------------------------------------------------------------
extern "C" void kernel_launch(void* const* d_in, const int* in_sizes, int n_in,
                              void* d_out, int out_size) {
    const float* zi = (const float*)d_in[0];
    const float* zj = (const float*)d_in[1];
    float* out = (float*)d_out;

    const int smem_bytes = (A_FLOATS + 2 * B_FLOATS) * 4;   // 141312
    cudaFuncSetAttribute(nt_main, cudaFuncAttributeMaxDynamicSharedMemorySize, smem_bytes);

    nt_normalize<<<NTOT / 8, 256>>>(zi, zj);
    nt_pos<<<NB / 8, 256>>>();
    nt_main<<<NTOT / BM, 256, smem_bytes>>>();
    nt_finalize<<<1, 256>>>(out);
}

// round 9
// speedup vs baseline: 2.8768x; 1.2538x over previous
#include <cuda_runtime.h>
#include <cuda_bf16.h>
#include <math.h>
#include <stdint.h>

#define NB    8192
#define DIM   128
#define NTOT  16384
#define INVT  14.285714285714286f

#define BM 128
#define BN 256
#define NT (NTOT/BN)              // 64 N-tiles per CTA

#define STRB 272                  // smem row stride in bytes (128 bf16 + 8 pad)
#define A_BYTES (128*STRB)        // 34816
#define B_BYTES (256*STRB)        // 69632 per buffer
#define SMEM_REQ (A_BYTES + 2*B_BYTES)   // 174080

__device__ __nv_bfloat16 g_repsb[(size_t)NTOT * DIM];   // 4 MB, L2-resident
__device__ float g_lse[NTOT];
__device__ float g_pos[NB];

// ---------------------------------------------------------------------------
__device__ __forceinline__ uint32_t smem_u32(const void* p) {
    uint32_t r;
    asm("{ .reg .u64 t; cvta.to.shared.u64 t, %1; cvt.u32.u64 %0, t; }" : "=r"(r) : "l"(p));
    return r;
}
__device__ __forceinline__ void cp16(uint32_t dst, const void* src) {
    asm volatile("cp.async.cg.shared.global [%0], [%1], 16;" :: "r"(dst), "l"(src));
}
__device__ __forceinline__ void cp_commit() { asm volatile("cp.async.commit_group;"); }
__device__ __forceinline__ void cp_wait0()  { asm volatile("cp.async.wait_group 0;"); }

__device__ __forceinline__ void ldsm4(uint32_t r[4], uint32_t addr) {
    asm volatile("ldmatrix.sync.aligned.m8n8.x4.shared.b16 {%0,%1,%2,%3}, [%4];"
        : "=r"(r[0]), "=r"(r[1]), "=r"(r[2]), "=r"(r[3]) : "r"(addr));
}
__device__ __forceinline__ void mma16816(float c[4], const uint32_t a[4],
                                         uint32_t b0, uint32_t b1) {
    asm volatile(
        "mma.sync.aligned.m16n8k16.row.col.f32.bf16.bf16.f32 "
        "{%0,%1,%2,%3}, {%4,%5,%6,%7}, {%8,%9}, {%0,%1,%2,%3};"
        : "+f"(c[0]), "+f"(c[1]), "+f"(c[2]), "+f"(c[3])
        : "r"(a[0]), "r"(a[1]), "r"(a[2]), "r"(a[3]), "r"(b0), "r"(b1));
}

// ---------------------------------------------------------------------------
// Normalize rows of [z_i; z_j] -> bf16(rn). One warp per row.
// ---------------------------------------------------------------------------
__global__ void nt_normalize(const float* __restrict__ zi,
                             const float* __restrict__ zj) {
    int row  = (blockIdx.x * blockDim.x + threadIdx.x) >> 5;
    int lane = threadIdx.x & 31;
    if (row >= NTOT) return;
    const float* src = (row < NB) ? (zi + (size_t)row * DIM)
                                  : (zj + (size_t)(row - NB) * DIM);
    float4 v = ((const float4*)src)[lane];
    float ss = v.x*v.x + v.y*v.y + v.z*v.z + v.w*v.w;
#pragma unroll
    for (int o = 16; o; o >>= 1) ss += __shfl_xor_sync(0xffffffffu, ss, o);
    float inv = 1.0f / fmaxf(sqrtf(ss), 1e-12f);
    __nv_bfloat162 p0, p1;
    p0.x = __float2bfloat16_rn(v.x*inv); p0.y = __float2bfloat16_rn(v.y*inv);
    p1.x = __float2bfloat16_rn(v.z*inv); p1.y = __float2bfloat16_rn(v.w*inv);
    __nv_bfloat162* dst = (__nv_bfloat162*)(g_repsb + (size_t)row * DIM);
    dst[lane*2]   = p0;
    dst[lane*2+1] = p1;
}

// ---------------------------------------------------------------------------
// pos[i] = exp(dot(zi_i/|zi_i|, zj_i/|zj_i|) / T)   (exact fp32 path)
// ---------------------------------------------------------------------------
__global__ void nt_pos(const float* __restrict__ zi,
                       const float* __restrict__ zj) {
    int row  = (blockIdx.x * blockDim.x + threadIdx.x) >> 5;
    int lane = threadIdx.x & 31;
    if (row >= NB) return;
    float4 a = ((const float4*)(zi + (size_t)row * DIM))[lane];
    float4 b = ((const float4*)(zj + (size_t)row * DIM))[lane];
    float sa = a.x*a.x + a.y*a.y + a.z*a.z + a.w*a.w;
    float sb = b.x*b.x + b.y*b.y + b.z*b.z + b.w*b.w;
    float d  = a.x*b.x + a.y*b.y + a.z*b.z + a.w*b.w;
#pragma unroll
    for (int o = 16; o; o >>= 1) {
        sa += __shfl_xor_sync(0xffffffffu, sa, o);
        sb += __shfl_xor_sync(0xffffffffu, sb, o);
        d  += __shfl_xor_sync(0xffffffffu, d,  o);
    }
    if (lane == 0) {
        float na = fmaxf(sqrtf(sa), 1e-12f);
        float nb = fmaxf(sqrtf(sb), 1e-12f);
        g_pos[row] = expf(d / (na * nb) * INVT);
    }
}

// ---------------------------------------------------------------------------
// Fused bf16 mma.sync GEMM + online double-logsumexp.
// CTA: 128 rows x 64 tiles of 256 cols. 8 warps = 2(M) x 4(N), warp tile 64x64.
// K=128 in one shot per tile (8 k16 steps); B tiles double-buffered (cp.async).
// ---------------------------------------------------------------------------
__global__ void __launch_bounds__(256, 1) nt_main() {
    extern __shared__ char smraw[];
    const uint32_t sA = smem_u32(smraw);
    const uint32_t sB = sA + A_BYTES;
    float* smf = (float*)smraw;

    const int tid   = threadIdx.x;
    const int lane  = tid & 31;
    const int wid   = tid >> 5;
    const int warpM = wid >> 2;       // 0..1
    const int warpN = wid & 3;        // 0..3
    const int mi    = lane >> 3;      // ldmatrix quadrant
    const int ri    = lane & 7;
    const int rt    = lane >> 2;      // C frag row
    const int qt    = lane & 3;       // C frag col pair
    const int r0    = blockIdx.x * BM;

    // ---- A block (128x128 bf16) -> smem
#pragma unroll
    for (int i = 0; i < 8; ++i) {
        int u = tid + i * 256;            // 0..2047
        int row = u >> 4, kq = u & 15;
        cp16(sA + (uint32_t)(row * STRB + kq * 16),
             g_repsb + (size_t)(r0 + row) * DIM + kq * 8);
    }
    // ---- B tile 0 -> buffer 0
#pragma unroll
    for (int i = 0; i < 16; ++i) {
        int u = tid + i * 256;            // 0..4095
        int n = u >> 4, kq = u & 15;
        cp16(sB + (uint32_t)(n * STRB + kq * 16),
             g_repsb + (size_t)n * DIM + kq * 8);
    }
    cp_commit();

    // ldmatrix lane addresses (byte offsets; +ks*32 per k16 step)
    uint32_t aAddr[4];
#pragma unroll
    for (int mt = 0; mt < 4; ++mt)
        aAddr[mt] = sA + (uint32_t)((warpM*64 + mt*16 + (mi & 1)*8 + ri) * STRB
                                    + (mi >> 1) * 16);
    uint32_t bOff[4];
#pragma unroll
    for (int np = 0; np < 4; ++np)
        bOff[np] = (uint32_t)((warpN*64 + np*16 + (mi >> 1)*8 + ri) * STRB
                              + (mi & 1) * 16);

    float C[4][8][4];
#pragma unroll
    for (int mt = 0; mt < 4; ++mt)
#pragma unroll
        for (int nt = 0; nt < 8; ++nt)
#pragma unroll
            for (int e = 0; e < 4; ++e) C[mt][nt][e] = 0.f;

    float Mx[8], Sx[8], thr[8];
#pragma unroll
    for (int s = 0; s < 8; ++s) { Mx[s] = -1e30f; Sx[s] = 0.f; thr[s] = -1e30f; }

    for (int t = 0; t < NT; ++t) {
        const uint32_t bufB = sB + (uint32_t)(t & 1) * B_BYTES;
        cp_wait0();
        __syncthreads();                  // tile t visible; prev compute done

        // prefetch tile t+1 into the other buffer (overlaps compute)
        if (t + 1 < NT) {
            const uint32_t nbB = sB + (uint32_t)((t + 1) & 1) * B_BYTES;
            const int c0n = (t + 1) * BN;
#pragma unroll
            for (int i = 0; i < 16; ++i) {
                int u = tid + i * 256;
                int n = u >> 4, kq = u & 15;
                cp16(nbB + (uint32_t)(n * STRB + kq * 16),
                     g_repsb + (size_t)(c0n + n) * DIM + kq * 8);
            }
        }
        cp_commit();

        // ---- compute: 8 k16 steps
#pragma unroll
        for (int ks = 0; ks < 8; ++ks) {
            uint32_t a[4][4], b[4][4];
#pragma unroll
            for (int mt = 0; mt < 4; ++mt) ldsm4(a[mt], aAddr[mt] + ks * 32);
#pragma unroll
            for (int np = 0; np < 4; ++np) ldsm4(b[np], bufB + bOff[np] + ks * 32);
            // b[np] = {b0(n even), b1(n even), b0(n odd), b1(n odd)}
#pragma unroll
            for (int mt = 0; mt < 4; ++mt)
#pragma unroll
                for (int np = 0; np < 4; ++np) {
                    mma16816(C[mt][np*2],     a[mt], b[np][0], b[np][1]);
                    mma16816(C[mt][np*2 + 1], a[mt], b[np][2], b[np][3]);
                }
        }

        // ---- epilogue: online (M, S, thr) update over this 256-col tile
        const int c0 = t * BN;
#pragma unroll
        for (int s = 0; s < 8; ++s) {
            const int mt = s >> 1, h = s & 1;
            const int grow = r0 + warpM*64 + mt*16 + rt + 8*h;
            float v[16];
            float tmax = -1e30f;
#pragma unroll
            for (int nt = 0; nt < 8; ++nt) {
#pragma unroll
                for (int e = 0; e < 2; ++e) {
                    float sv = C[mt][nt][h*2 + e] * INVT;
                    int col = c0 + warpN*64 + nt*8 + 2*qt + e;
                    if (col == grow) sv = -1e30f;          // mask diagonal
                    v[nt*2 + e] = sv;
                    tmax = fmaxf(tmax, sv);
                }
            }
            if (tmax > Mx[s]) {
                float mo = __expf(Mx[s]);
                float mn = __expf(tmax);
                Sx[s] *= __expf(mo - mn);                  // underflows safely
                Mx[s] = tmax;
                thr[s] = (mn > 26.f) ? __logf(mn - 25.f) : -1e30f;
            }
            if (tmax > thr[s]) {                           // rare after warm-up
                const float eM = __expf(Mx[s]);
#pragma unroll
                for (int j = 0; j < 16; ++j)
                    if (v[j] > thr[s])
                        Sx[s] += __expf(__expf(v[j]) - eM);
            }
        }
#pragma unroll
        for (int mt = 0; mt < 4; ++mt)
#pragma unroll
            for (int nt = 0; nt < 8; ++nt)
#pragma unroll
                for (int e = 0; e < 4; ++e) C[mt][nt][e] = 0.f;
    }

    // ---- combine the 16 partials per row (4 N-warps x 4 lane-cols)
    __syncthreads();
    float* shM = smf;
    float* shS = smf + 2048;
#pragma unroll
    for (int s = 0; s < 8; ++s) {
        const int mt = s >> 1, h = s & 1;
        const int lrow = warpM*64 + mt*16 + rt + 8*h;
        shM[lrow * 16 + warpN * 4 + qt] = Mx[s];
        shS[lrow * 16 + warpN * 4 + qt] = Sx[s];
    }
    __syncthreads();
    if (tid < 128) {
        float bm = -1e30f, bs = 0.f;
#pragma unroll
        for (int t = 0; t < 16; ++t) {
            float Mi = shM[tid * 16 + t];
            float Si = shS[tid * 16 + t];
            if (Mi > bm) {
                bs = bs * __expf(__expf(bm) - __expf(Mi)) + Si;
                bm = Mi;
            } else {
                bs += Si * __expf(__expf(Mi) - __expf(bm));
            }
        }
        g_lse[r0 + tid] = __expf(bm) + logf(bs);   // lse = e_max + log(S)
    }
}

// ---------------------------------------------------------------------------
// Final scalar: mean(lse - pos), fp64 accumulation.
// ---------------------------------------------------------------------------
__global__ void nt_finalize(float* __restrict__ out) {
    __shared__ double red[1024];
    double acc = 0.0;
    for (int i = threadIdx.x; i < NTOT; i += 1024) {
        float pos = g_pos[(i < NB) ? i : (i - NB)];
        acc += (double)g_lse[i] - (double)pos;
    }
    red[threadIdx.x] = acc;
    __syncthreads();
    for (int s = 512; s; s >>= 1) {
        if (threadIdx.x < s) red[threadIdx.x] += red[threadIdx.x + s];
        __syncthreads();
    }
    if (threadIdx.x == 0) out[0] = (float)(red[0] / (double)NTOT);
}

// ---------------------------------------------------------------------------
extern "C" void kernel_launch(void* const* d_in, const int* in_sizes, int n_in,
                              void* d_out, int out_size) {
    const float* zi = (const float*)d_in[0];
    const float* zj = (const float*)d_in[1];
    float* out = (float*)d_out;

    cudaFuncSetAttribute(nt_main, cudaFuncAttributeMaxDynamicSharedMemorySize, SMEM_REQ);

    nt_normalize<<<NTOT / 8, 256>>>(zi, zj);
    nt_pos<<<NB / 8, 256>>>(zi, zj);
    nt_main<<<NTOT / BM, 256, SMEM_REQ>>>();
    nt_finalize<<<1, 1024>>>(out);
}